// round 14
// baseline (speedup 1.0000x reference)
#include <cuda_runtime.h>
#include <cuda_fp16.h>
#include <cstdint>
#include <math.h>

// Problem constants
#define BATCH 32
#define NQ    1024
#define NK    2048
#define DMODEL 256

// ---- fp16 GEMM constants ----
#define BM 128
#define BN 128
#define BKH 64
#define LDSH 72                    // B-tile / logits stride (halves)
#define LDA4 264                   // persistent A-tile stride (halves), 528B rows
#define HA_TILE (128 * LDA4)       // persistent A tile (halves) = 67584B
#define TILE_H (128 * LDSH)        // 18432B per 128x64 tile
#define BUFSTR_H (2 * TILE_H)
#define SMEM_H (2 * BUFSTR_H * 2)  // logits smem: 73728 B
#define SMEM_P ((HA_TILE + 2 * TILE_H) * 2)   // proj smem: 104448 B
#define LDS2 132

// ---- out kernel (BM=64) ----
#define TILE_A64 (64 * LDSH)
#define BUFSTR_O (TILE_A64 + TILE_H)
#define SMEM_O (2 * BUFSTR_O * 2 + 512)

// Scratch (static device memory — allocation-free per harness rules)
__device__ __half g_q   [BATCH * NQ * DMODEL];       // t = Xq @ G/16  (fp16)
__device__ __half g_k   [BATCH * NK * DMODEL];       // Xk fp16
__device__ __half g_vT  [BATCH * DMODEL * NK];       // v transposed [b][d][k]
__device__ __half g_e   [(size_t)BATCH * NQ * NK];   // fp16 unnormalized exp(logits)
__device__ float  g_psum[BATCH * 16 * NQ];
__device__ __half g_Gt  [256 * 256];                 // Gt[e][c] = sum_d Wk[d,e]Wq[d,c]/16
__device__ __half g_wvh [256 * 256];                 // Wv fp16
__device__ float  g_wu256[256];
__device__ float  g_wv256[256];
__device__ float  g_c0_arr[1];
__device__ float  g_u[BATCH * NQ];
__device__ float  g_v[BATCH * NK];

__device__ __forceinline__ void mma_f16(float c[4], const uint32_t a[4], const uint32_t b[2]) {
    asm("mma.sync.aligned.m16n8k16.row.col.f32.f16.f16.f32 "
        "{%0,%1,%2,%3}, {%4,%5,%6,%7}, {%8,%9}, {%0,%1,%2,%3};"
        : "+f"(c[0]), "+f"(c[1]), "+f"(c[2]), "+f"(c[3])
        : "r"(a[0]), "r"(a[1]), "r"(a[2]), "r"(a[3]), "r"(b[0]), "r"(b[1]));
}

__device__ __forceinline__ void ldsm_x4(uint32_t r[4], uint32_t addr) {
    asm volatile("ldmatrix.sync.aligned.m8n8.x4.shared.b16 {%0,%1,%2,%3}, [%4];"
                 : "=r"(r[0]), "=r"(r[1]), "=r"(r[2]), "=r"(r[3]) : "r"(addr));
}

__device__ __forceinline__ void cp_async16(const void* smem, const void* gmem) {
    uint32_t s = (uint32_t)__cvta_generic_to_shared(smem);
    asm volatile("cp.async.cg.shared.global [%0], [%1], 16;" :: "r"(s), "l"(gmem) : "memory");
}
__device__ __forceinline__ void cp_commit() { asm volatile("cp.async.commit_group;" ::: "memory"); }
template<int N> __device__ __forceinline__ void cp_wait() {
    asm volatile("cp.async.wait_group %0;" :: "n"(N) : "memory");
}
__device__ __forceinline__ void stcs_u2(void* p, uint2 v) {
    asm volatile("st.global.cs.v2.u32 [%0], {%1, %2};" :: "l"(p), "r"(v.x), "r"(v.y) : "memory");
}
__device__ __forceinline__ void stcs_f4(void* p, float4 v) {
    asm volatile("st.global.cs.v4.f32 [%0], {%1, %2, %3, %4};"
                 :: "l"(p), "f"(v.x), "f"(v.y), "f"(v.z), "f"(v.w) : "memory");
}

// ---------------- prep kernel: G^T (fp16), wu, wv, c0, Wv fp16 ----------------
__global__ void __launch_bounds__(256) prep_kernel(const float* __restrict__ Wq,
                                                   const float* __restrict__ Wk,
                                                   const float* __restrict__ bq,
                                                   const float* __restrict__ bk,
                                                   const float* __restrict__ Wv) {
    const int bx = blockIdx.x, tid = threadIdx.x;
    if (bx < 256) {
        int e = bx;
        float acc = 0.f;
        for (int d = 0; d < 256; d++)
            acc += Wk[d * 256 + e] * Wq[d * 256 + tid];
        g_Gt[e * 256 + tid] = __float2half_rn(acc * 0.0625f);
    } else if (bx == 256) {
        float acc = 0.f;
        for (int d = 0; d < 256; d++) acc += Wq[d * 256 + tid] * bk[d];
        g_wu256[tid] = acc * 0.0625f;
    } else if (bx == 257) {
        float acc = 0.f;
        for (int d = 0; d < 256; d++) acc += Wk[d * 256 + tid] * bq[d];
        g_wv256[tid] = acc * 0.0625f;
    } else if (bx == 258) {
        __shared__ float red[256];
        red[tid] = bq[tid] * bk[tid];
        __syncthreads();
        for (int s = 128; s; s >>= 1) { if (tid < s) red[tid] += red[tid + s]; __syncthreads(); }
        if (tid == 0) g_c0_arr[0] = red[0] * 0.0625f;
    } else {
        int base = (bx - 259) * 4096 + tid;     // 16 blocks x 4096 = 65536
#pragma unroll
        for (int i = 0; i < 16; i++)
            g_wvh[base + i * 256] = __float2half_rn(Wv[base + i * 256]);
    }
}

// ---------------- aux kernel: key -> fp16 + v-dot ----------------
__global__ void __launch_bounds__(256) aux_kernel(const float* __restrict__ key) {
    const long long row = (long long)blockIdx.x * 8 + (threadIdx.x >> 5);
    const int lane = threadIdx.x & 31;
    const float* xr = key + row * 256;
    float4 a  = __ldcs(reinterpret_cast<const float4*>(&xr[lane * 4]));
    float4 b2 = __ldcs(reinterpret_cast<const float4*>(&xr[128 + lane * 4]));

    __half2 h0 = __halves2half2(__float2half_rn(a.x),  __float2half_rn(a.y));
    __half2 h1 = __halves2half2(__float2half_rn(a.z),  __float2half_rn(a.w));
    __half2 h2 = __halves2half2(__float2half_rn(b2.x), __float2half_rn(b2.y));
    __half2 h3 = __halves2half2(__float2half_rn(b2.z), __float2half_rn(b2.w));
    uint2 p0, p1;
    p0.x = *reinterpret_cast<uint32_t*>(&h0);
    p0.y = *reinterpret_cast<uint32_t*>(&h1);
    p1.x = *reinterpret_cast<uint32_t*>(&h2);
    p1.y = *reinterpret_cast<uint32_t*>(&h3);
    *reinterpret_cast<uint2*>(&g_k[row * 256 + lane * 4])       = p0;
    *reinterpret_cast<uint2*>(&g_k[row * 256 + 128 + lane * 4]) = p1;

    float4 wa = *reinterpret_cast<const float4*>(&g_wv256[lane * 4]);
    float4 wb = *reinterpret_cast<const float4*>(&g_wv256[128 + lane * 4]);
    float dot = a.x * wa.x + a.y * wa.y + a.z * wa.z + a.w * wa.w
              + b2.x * wb.x + b2.y * wb.y + b2.z * wb.z + b2.w * wb.w;
#pragma unroll
    for (int o = 16; o; o >>= 1) dot += __shfl_xor_sync(0xffffffffu, dot, o);
    if (lane == 0) g_v[row] = dot;
}

// ======================= fp16 GEMM path =======================

__device__ __forceinline__ void load_tile_h(const __half* a, long long lda,
                                            const __half* b, long long ldb,
                                            __half* sA, __half* sB) {
#pragma unroll
    for (int r = 0; r < 128; r += 32) {
        cp_async16(sA + r * LDSH, a + (long long)r * lda);
        cp_async16(sB + r * LDSH, b + (long long)r * ldb);
    }
    cp_commit();
}

// Warp tile 32x64, ldmatrix fragment loads. A-tile 128 rows, stride LDSH.
__device__ __forceinline__ void mma_stage_h(const __half* cA, const __half* cB,
                                            int wm, int wn, int lane,
                                            float (&acc)[2][8][4]) {
    const int lrow16 = lane & 15;
    const int lkoff  = (lane >> 4) << 3;
    uint32_t aAddr = (uint32_t)__cvta_generic_to_shared(
        cA + (wm * 32 + lrow16) * LDSH + lkoff);
    uint32_t bAddr = (uint32_t)__cvta_generic_to_shared(
        cB + (wn * 64 + lrow16) * LDSH + lkoff);
#pragma unroll
    for (int kk = 0; kk < BKH; kk += 16) {
        uint32_t a0[4], a1[4];
        ldsm_x4(a0, aAddr + kk * 2);
        ldsm_x4(a1, aAddr + 16 * LDSH * 2 + kk * 2);
#pragma unroll
        for (int ni2 = 0; ni2 < 4; ni2++) {
            uint32_t bb[4];
            ldsm_x4(bb, bAddr + ni2 * 16 * LDSH * 2 + kk * 2);
            uint32_t be[2] = { bb[0], bb[2] };
            uint32_t bo[2] = { bb[1], bb[3] };
            mma_f16(acc[0][ni2 * 2],     a0, be);
            mma_f16(acc[1][ni2 * 2],     a1, be);
            mma_f16(acc[0][ni2 * 2 + 1], a0, bo);
            mma_f16(acc[1][ni2 * 2 + 1], a1, bo);
        }
    }
}

// Warp tile 32x64, persistent A-tile (stride LDA4, k-offset kbase).
__device__ __forceinline__ void mma_stage_pa(const __half* sA, int kbase,
                                             const __half* cB,
                                             int wm, int wn, int lane,
                                             float (&acc)[2][8][4]) {
    const int lrow16 = lane & 15;
    const int lkoff  = (lane >> 4) << 3;
    uint32_t aAddr = (uint32_t)__cvta_generic_to_shared(
        sA + (wm * 32 + lrow16) * LDA4 + kbase + lkoff);
    uint32_t bAddr = (uint32_t)__cvta_generic_to_shared(
        cB + (wn * 64 + lrow16) * LDSH + lkoff);
#pragma unroll
    for (int kk = 0; kk < BKH; kk += 16) {
        uint32_t a0[4], a1[4];
        ldsm_x4(a0, aAddr + kk * 2);
        ldsm_x4(a1, aAddr + 16 * LDA4 * 2 + kk * 2);
#pragma unroll
        for (int ni2 = 0; ni2 < 4; ni2++) {
            uint32_t bb[4];
            ldsm_x4(bb, bAddr + ni2 * 16 * LDSH * 2 + kk * 2);
            uint32_t be[2] = { bb[0], bb[2] };
            uint32_t bo[2] = { bb[1], bb[3] };
            mma_f16(acc[0][ni2 * 2],     a0, be);
            mma_f16(acc[1][ni2 * 2],     a1, be);
            mma_f16(acc[0][ni2 * 2 + 1], a0, bo);
            mma_f16(acc[1][ni2 * 2 + 1], a1, bo);
        }
    }
}

// ---------------- proj kernel (fp32 inputs direct, persistent fp16 A-tile) ----------------
// z = 0: t = Xq @ Gt -> g_q fp16 (grid.x < 256); also writes g_u (fused u-dot)
// z = 1: v = Xv @ Wv + bv -> g_vT fp16 (transposed)
__global__ void __launch_bounds__(256) proj_kernel(const float* __restrict__ query,
                                                   const float* __restrict__ value,
                                                   const float* __restrict__ bv) {
    extern __shared__ __half smemh[];
    const int z = blockIdx.z;
    if (z == 0 && blockIdx.x >= BATCH * NQ / BM) return;

    const float* Asrc = z ? value : query;
    const __half* Bsrc = z ? g_wvh : g_Gt;

    const int tid = threadIdx.x, warp = tid >> 5, lane = tid & 31;
    const int wm = warp >> 1, wn = warp & 1, g = lane >> 2, tg = lane & 3;
    const int m0 = blockIdx.x * BM, n0 = blockIdx.y * BN;

    // ---- B pipeline setup (cp.async into 2 stages after the persistent A tile) ----
    const int lrowB = tid >> 3;
    const int lcolB = (tid & 7) << 3;
    const __half* Bg = Bsrc + (long long)(n0 + lrowB) * DMODEL + lcolB;
    __half* sB0 = smemh + HA_TILE + lrowB * LDSH + lcolB;

    // stage 0 of B
#pragma unroll
    for (int r = 0; r < 128; r += 32) cp_async16(sB0 + r * LDSH, Bg + (long long)r * DMODEL);
    cp_commit();

    // ---- persistent A tile: LDG fp32 -> cvt -> STS fp16 (+ fused u-dot for z=0) ----
    {
        const int rr = tid >> 1, hh = tid & 1;        // row 0..127, half 0/1
        const float* src = Asrc + (long long)(m0 + rr) * DMODEL + hh * 128;
        __half* dst = smemh + rr * LDA4 + hh * 128;
        const float4* wup = reinterpret_cast<const float4*>(g_wu256 + hh * 128);
        float dot = 0.f;
#pragma unroll
        for (int j = 0; j < 16; j++) {
            float4 f0 = __ldcs(reinterpret_cast<const float4*>(src + j * 8));
            float4 f1 = __ldcs(reinterpret_cast<const float4*>(src + j * 8 + 4));
            if (z == 0) {
                float4 w0 = wup[j * 2], w1 = wup[j * 2 + 1];
                dot += f0.x * w0.x + f0.y * w0.y + f0.z * w0.z + f0.w * w0.w
                     + f1.x * w1.x + f1.y * w1.y + f1.z * w1.z + f1.w * w1.w;
            }
            __half2 h0 = __halves2half2(__float2half_rn(f0.x), __float2half_rn(f0.y));
            __half2 h1 = __halves2half2(__float2half_rn(f0.z), __float2half_rn(f0.w));
            __half2 h2 = __halves2half2(__float2half_rn(f1.x), __float2half_rn(f1.y));
            __half2 h3 = __halves2half2(__float2half_rn(f1.z), __float2half_rn(f1.w));
            uint4 pk;
            pk.x = *reinterpret_cast<uint32_t*>(&h0);
            pk.y = *reinterpret_cast<uint32_t*>(&h1);
            pk.z = *reinterpret_cast<uint32_t*>(&h2);
            pk.w = *reinterpret_cast<uint32_t*>(&h3);
            *reinterpret_cast<uint4*>(dst + j * 8) = pk;
        }
        if (z == 0) {
            dot += __shfl_xor_sync(0xffffffffu, dot, 1);   // combine the two halves
            if (hh == 0) g_u[m0 + rr] = dot;               // idempotent across n0 CTAs
        }
    }

    // stage 1 of B
#pragma unroll
    for (int r = 0; r < 128; r += 32)
        cp_async16(sB0 + TILE_H + r * LDSH, Bg + BKH + (long long)r * DMODEL);
    cp_commit();

    float acc[2][8][4] = {};
    const int kt = DMODEL / BKH;   // 4

    for (int it = 0; it < kt; ++it) {
        if (it + 2 < kt) {
            // refill buffer (it & 1) AFTER it's consumed — but consumption is this
            // iteration; so issue for it+2 after the mma sync below instead.
        }
        if (it + 1 < kt) cp_wait<1>(); else cp_wait<0>();
        __syncthreads();
        mma_stage_pa(smemh, it * BKH,
                     smemh + HA_TILE + (it & 1) * TILE_H,
                     wm, wn, lane, acc);
        __syncthreads();
        if (it + 2 < kt) {
#pragma unroll
            for (int r = 0; r < 128; r += 32)
                cp_async16(sB0 + (it & 1) * TILE_H + r * LDSH,
                           Bg + (it + 2) * BKH + (long long)r * DMODEL);
            cp_commit();
        }
    }

    // ---- epilogue ----
#pragma unroll
    for (int mi = 0; mi < 2; mi++) {
#pragma unroll
        for (int half = 0; half < 2; half++) {
            int r = m0 + wm * 32 + mi * 16 + g + half * 8;
#pragma unroll
            for (int ni = 0; ni < 8; ni++) {
                int c = n0 + wn * 64 + ni * 8 + tg * 2;
                if (z == 0) {
                    __half h0 = __float2half_rn(acc[mi][ni][half * 2 + 0]);
                    __half h1 = __float2half_rn(acc[mi][ni][half * 2 + 1]);
                    *reinterpret_cast<__half2*>(&g_q[(long long)r * DMODEL + c]) =
                        __halves2half2(h0, h1);
                } else {
                    float v0 = acc[mi][ni][half * 2 + 0] + bv[c];
                    float v1 = acc[mi][ni][half * 2 + 1] + bv[c + 1];
                    long long bidx = r >> 11;               // NK = 2048
                    long long tk = r & (NK - 1);
                    g_vT[(bidx * DMODEL + c) * NK + tk]     = __float2half_rn(v0);
                    g_vT[(bidx * DMODEL + c + 1) * NK + tk] = __float2half_rn(v1);
                }
            }
        }
    }
}

// Shared fp16 K=256 mainloop (logits)
__device__ __forceinline__ void gemm_loop_h256(const __half* __restrict__ A, long long lda,
                                               const __half* __restrict__ B, long long ldb,
                                               int m0, int n0,
                                               float (&acc)[2][8][4], __half* smemh,
                                               int wm, int wn, int lane,
                                               int lrow, int lcol) {
    const __half* Ag = A + (long long)(m0 + lrow) * lda + lcol;
    const __half* Bg = B + (long long)(n0 + lrow) * ldb + lcol;
    __half* sA0 = smemh + lrow * LDSH + lcol;
    __half* sB0 = smemh + TILE_H + lrow * LDSH + lcol;

    const int kt = DMODEL / BKH;   // 4
    load_tile_h(Ag, lda, Bg, ldb, sA0, sB0);
    for (int it = 0; it < kt; ++it) {
        int nxt = (it + 1) & 1;
        if (it + 1 < kt) {
            load_tile_h(Ag + (it + 1) * BKH, lda, Bg + (it + 1) * BKH, ldb,
                        sA0 + nxt * BUFSTR_H, sB0 + nxt * BUFSTR_H);
            cp_wait<1>();
        } else {
            cp_wait<0>();
        }
        __syncthreads();
        mma_stage_h(smemh + (it & 1) * BUFSTR_H,
                    smemh + (it & 1) * BUFSTR_H + TILE_H,
                    wm, wn, lane, acc);
        __syncthreads();
    }
}

// ---------------- Logits kernel (fp16, + u/v/c bilinear terms) ----------------
__global__ void __launch_bounds__(256) logits_kernel(const float* __restrict__ bias,
                                                     const int* __restrict__ qmask,
                                                     const int* __restrict__ kmask) {
    extern __shared__ __half smemh[];
    const int b = blockIdx.z;
    const int m0 = blockIdx.x * BM, n0 = blockIdx.y * BN;

    const int tid  = threadIdx.x;
    const int warp = tid >> 5, lane = tid & 31;
    const int wm = warp >> 1, wn = warp & 1;
    const int g  = lane >> 2, tg = lane & 3;
    const int lrow = tid >> 3;
    const int lcol = (tid & 7) << 3;

    float acc[2][8][4] = {};
    gemm_loop_h256(g_q + (long long)b * NQ * DMODEL, DMODEL,
                   g_k + (long long)b * NK * DMODEL, DMODEL,
                   m0, n0, acc, smemh, wm, wn, lane, lrow, lcol);

    // scatter raw (already /16-scaled) logit mains to fp32 smem tile
    float* st = reinterpret_cast<float*>(smemh);
#pragma unroll
    for (int mi = 0; mi < 2; mi++) {
#pragma unroll
        for (int half = 0; half < 2; half++) {
            int rl = wm * 32 + mi * 16 + half * 8 + g;
#pragma unroll
            for (int ni = 0; ni < 8; ni++) {
                int c = wn * 64 + ni * 8 + tg * 2;
                st[rl * LDS2 + c]     = acc[mi][ni][half * 2 + 0];
                st[rl * LDS2 + c + 1] = acc[mi][ni][half * 2 + 1];
            }
        }
    }
    __syncthreads();

    const int4 km4 = *reinterpret_cast<const int4*>(&kmask[b * NK + n0 + lane * 4]);
    const int* qm = qmask + b * NQ;
    const float* bb = bias + ((long long)b * NQ + m0) * NK + n0;
    __half* eb = g_e + ((long long)b * NQ + m0) * NK + n0;
    const float c0 = g_c0_arr[0];
    const float4 v4 = *reinterpret_cast<const float4*>(&g_v[b * NK + n0 + lane * 4]);
    const float* up = g_u + (long long)b * NQ + m0;

#pragma unroll 4
    for (int rr = 0; rr < 16; rr++) {
        int rl = warp * 16 + rr;
        int qv = qm[m0 + rl];
        float uv = up[rl] + c0;
        float4 l4 = *reinterpret_cast<const float4*>(&st[rl * LDS2 + lane * 4]);
        float4 bv = __ldcs(reinterpret_cast<const float4*>(&bb[(long long)rl * NK + lane * 4]));
        float e0, e1, e2, e3;
        if (qv) {
            e0 = km4.x ? fminf(__expf(l4.x + bv.x + v4.x + uv), 60000.f) : 0.f;
            e1 = km4.y ? fminf(__expf(l4.y + bv.y + v4.y + uv), 60000.f) : 0.f;
            e2 = km4.z ? fminf(__expf(l4.z + bv.z + v4.z + uv), 60000.f) : 0.f;
            e3 = km4.w ? fminf(__expf(l4.w + bv.w + v4.w + uv), 60000.f) : 0.f;
        } else {
            e0 = e1 = e2 = e3 = 1.f;   // fully-masked row -> uniform softmax
        }
        __half2 h01 = __halves2half2(__float2half_rn(e0), __float2half_rn(e1));
        __half2 h23 = __halves2half2(__float2half_rn(e2), __float2half_rn(e3));
        uint2 packed;
        packed.x = *reinterpret_cast<uint32_t*>(&h01);
        packed.y = *reinterpret_cast<uint32_t*>(&h23);
        stcs_u2(&eb[(long long)rl * NK + lane * 4], packed);
        float vsum = __half2float(__low2half(h01)) + __half2float(__high2half(h01))
                   + __half2float(__low2half(h23)) + __half2float(__high2half(h23));
#pragma unroll
        for (int off = 16; off; off >>= 1)
            vsum += __shfl_xor_sync(0xffffffffu, vsum, off);
        if (lane == 0)
            g_psum[((b * 16 + blockIdx.y) << 10) + m0 + rl] = vsum;
    }
}

// ---------------- Output GEMM (fp16, BM=64, combine fused) ----------------
__global__ void __launch_bounds__(256) out_kernel(float* __restrict__ wout,
                                                  float* __restrict__ out) {
    extern __shared__ __half smemh[];
    float* sI = reinterpret_cast<float*>(smemh + 2 * BUFSTR_O);   // [64]

    const int b = blockIdx.z;
    const int m0 = blockIdx.x * 64, n0 = blockIdx.y * BN;
    const int tid = threadIdx.x;
    const int warp = tid >> 5, lane = tid & 31;
    const int wm = warp >> 2, wn = warp & 3;

    if (tid < 64) {
        float S = 0.f;
#pragma unroll
        for (int nt = 0; nt < 16; nt++)
            S += g_psum[((b * 16 + nt) << 10) + m0 + tid];
        sI[tid] = 1.0f / S;
    }

    const __half* A = g_e + (long long)b * NQ * NK;
    const __half* B = g_vT + (long long)b * DMODEL * NK;
    float* wb = wout + (long long)b * NQ * NK;
    const bool first_half = (n0 == 0);

    const int lrow = tid >> 3;
    const int lcol = (tid & 7) << 3;
    const __half* Ag = A + (long long)(m0 + lrow) * NK + lcol;
    const __half* Bg = B + (long long)(n0 + lrow) * NK + lcol;
    __half* sA0 = smemh + lrow * LDSH + lcol;
    __half* sB0 = smemh + TILE_A64 + lrow * LDSH + lcol;

    float acc[2][4][4] = {};
    const int kt = NK / BKH;   // 32

#define LOAD_TILE_O(koff, stg)                                                     \
    do {                                                                           \
        const __half* _a = Ag + (koff);                                            \
        const __half* _b = Bg + (koff);                                            \
        __half* _sa = sA0 + (stg) * BUFSTR_O;                                      \
        __half* _sb = sB0 + (stg) * BUFSTR_O;                                      \
        cp_async16(_sa, _a);                                                       \
        cp_async16(_sa + 32 * LDSH, _a + 32ll * NK);                               \
        cp_async16(_sb, _b);                                                       \
        cp_async16(_sb + 32 * LDSH, _b + 32ll * NK);                               \
        cp_async16(_sb + 64 * LDSH, _b + 64ll * NK);                               \
        cp_async16(_sb + 96 * LDSH, _b + 96ll * NK);                               \
        cp_commit();                                                               \
    } while (0)

    LOAD_TILE_O(0, 0);

    const int wrow = tid >> 2, wseg = tid & 3;

    for (int it = 0; it < kt; ++it) {
        int nxt = (it + 1) & 1;
        if (it + 1 < kt) {
            LOAD_TILE_O((it + 1) * BKH, nxt);
            cp_wait<1>();
        } else {
            cp_wait<0>();
        }
        __syncthreads();

        __half* bufA = smemh + (it & 1) * BUFSTR_O;
        __half* bufB = bufA + TILE_A64;

        if ((it < kt / 2) == first_half) {
            const int k0 = it * BKH;
            float rI = sI[wrow];
            float* wr = wb + (long long)(m0 + wrow) * NK + k0 + wseg * 16;
            const __half* src = bufA + wrow * LDSH + wseg * 16;
#pragma unroll
            for (int j = 0; j < 2; j++) {
                uint4 raw = *reinterpret_cast<const uint4*>(src + j * 8);
                __half2 p0 = *reinterpret_cast<__half2*>(&raw.x);
                __half2 p1 = *reinterpret_cast<__half2*>(&raw.y);
                __half2 p2 = *reinterpret_cast<__half2*>(&raw.z);
                __half2 p3 = *reinterpret_cast<__half2*>(&raw.w);
                float4 o0, o1;
                o0.x = __half2float(__low2half(p0)) * rI;
                o0.y = __half2float(__high2half(p0)) * rI;
                o0.z = __half2float(__low2half(p1)) * rI;
                o0.w = __half2float(__high2half(p1)) * rI;
                o1.x = __half2float(__low2half(p2)) * rI;
                o1.y = __half2float(__high2half(p2)) * rI;
                o1.z = __half2float(__low2half(p3)) * rI;
                o1.w = __half2float(__high2half(p3)) * rI;
                stcs_f4(wr + j * 8,     o0);
                stcs_f4(wr + j * 8 + 4, o1);
            }
        }

        {
            const int lrow16 = lane & 15;
            const int lkoff  = (lane >> 4) << 3;
            uint32_t aAddr = (uint32_t)__cvta_generic_to_shared(
                bufA + (wm * 32 + lrow16) * LDSH + lkoff);
            uint32_t bAddr = (uint32_t)__cvta_generic_to_shared(
                bufB + (wn * 32 + lrow16) * LDSH + lkoff);
#pragma unroll
            for (int kk = 0; kk < BKH; kk += 16) {
                uint32_t a0[4], a1[4];
                ldsm_x4(a0, aAddr + kk * 2);
                ldsm_x4(a1, aAddr + 16 * LDSH * 2 + kk * 2);
#pragma unroll
                for (int ni2 = 0; ni2 < 2; ni2++) {
                    uint32_t bbf[4];
                    ldsm_x4(bbf, bAddr + ni2 * 16 * LDSH * 2 + kk * 2);
                    uint32_t be[2] = { bbf[0], bbf[2] };
                    uint32_t bo[2] = { bbf[1], bbf[3] };
                    mma_f16(acc[0][ni2 * 2],     a0, be);
                    mma_f16(acc[1][ni2 * 2],     a1, be);
                    mma_f16(acc[0][ni2 * 2 + 1], a0, bo);
                    mma_f16(acc[1][ni2 * 2 + 1], a1, bo);
                }
            }
        }
        __syncthreads();
    }

    float* ob = out + (long long)b * NQ * DMODEL;
    const int g = lane >> 2, tg = lane & 3;
#pragma unroll
    for (int mi = 0; mi < 2; mi++) {
#pragma unroll
        for (int half = 0; half < 2; half++) {
            int rl = wm * 32 + mi * 16 + g + half * 8;
            int r = m0 + rl;
            float rI = sI[rl];
#pragma unroll
            for (int ni = 0; ni < 4; ni++) {
#pragma unroll
                for (int cj = 0; cj < 2; cj++) {
                    int c = n0 + wn * 32 + ni * 8 + tg * 2 + cj;
                    ob[(long long)r * DMODEL + c] = acc[mi][ni][half * 2 + cj] * rI;
                }
            }
        }
    }
}

extern "C" void kernel_launch(void* const* d_in, const int* in_sizes, int n_in,
                              void* d_out, int out_size) {
    (void)in_sizes; (void)n_in; (void)out_size;
    const float* query = (const float*)d_in[0];
    const float* key   = (const float*)d_in[1];
    const float* value = (const float*)d_in[2];
    const int*   qmask = (const int*)d_in[3];
    const int*   kmask = (const int*)d_in[4];
    const float* bias  = (const float*)d_in[5];
    const float* Wq = (const float*)d_in[6];
    const float* bq = (const float*)d_in[7];
    const float* Wk = (const float*)d_in[8];
    const float* bk = (const float*)d_in[9];
    const float* Wv = (const float*)d_in[10];
    const float* bv = (const float*)d_in[11];

    float* out = (float*)d_out;                                   // (B, NQ, D)
    float* w   = out + (size_t)BATCH * NQ * DMODEL;               // (B, NQ, NK)

    cudaFuncSetAttribute((const void*)proj_kernel,   cudaFuncAttributeMaxDynamicSharedMemorySize, SMEM_P);
    cudaFuncSetAttribute((const void*)logits_kernel, cudaFuncAttributeMaxDynamicSharedMemorySize, SMEM_H);
    cudaFuncSetAttribute((const void*)out_kernel,    cudaFuncAttributeMaxDynamicSharedMemorySize, SMEM_O);

    // G^T (fp16), wu, wv, c0, Wv fp16
    prep_kernel<<<275, 256>>>(Wq, Wk, bq, bk, Wv);

    // key -> fp16 + v-dot
    aux_kernel<<<BATCH * NK / 8, 256>>>(key);

    // t = Xq @ Gt (z=0, fused u-dot); v-proj (z=1). fp32 inputs read directly.
    proj_kernel<<<dim3(BATCH * NK / BM, DMODEL / BN, 2), 256, SMEM_P>>>(query, value, bv);

    // e = exp(t.Xk + u + v + c + bias) fp16 + per-tile row sums
    logits_kernel<<<dim3(NQ / BM, NK / BN, BATCH), 256, SMEM_H>>>(bias, qmask, kmask);

    // out = invS * (e @ v); combine fused; streams w = e * invS
    out_kernel<<<dim3(NQ / 64, DMODEL / BN, BATCH), 256, SMEM_O>>>(w, out);
}

// round 15
// speedup vs baseline: 1.1475x; 1.1475x over previous
#include <cuda_runtime.h>
#include <cuda_fp16.h>
#include <cstdint>
#include <math.h>

// Problem constants
#define BATCH 32
#define NQ    1024
#define NK    2048
#define DMODEL 256

// ---- fp16 GEMM constants ----
#define BM 128
#define BN 128
#define BKH 64
#define LDSH 72
#define TILE_H (128 * LDSH)
#define BUFSTR_H (2 * TILE_H)
#define SMEM_H (2 * BUFSTR_H * 2)
#define LDS2 132

// ---- out kernel (BM=64) ----
#define TILE_A64 (64 * LDSH)
#define BUFSTR_O (TILE_A64 + TILE_H)
#define SMEM_O (2 * BUFSTR_O * 2 + 512)

// Scratch (static device memory — allocation-free per harness rules)
__device__ __half g_q   [BATCH * NQ * DMODEL];       // t = Xq @ G/16  (fp16)
__device__ __half g_k   [BATCH * NK * DMODEL];       // Xk fp16
__device__ __half g_xq  [BATCH * NQ * DMODEL];       // Xq fp16
__device__ __half g_xv  [BATCH * NK * DMODEL];       // Xv fp16
__device__ __half g_vT  [BATCH * DMODEL * NK];       // v transposed [b][d][k]
__device__ __half g_e   [(size_t)BATCH * NQ * NK];   // fp16 unnormalized exp(logits)
__device__ float  g_psum[BATCH * 16 * NQ];
__device__ __half g_Gt  [256 * 256];                 // Gt[e][c] = sum_d Wk[d,e]Wq[d,c]/16
__device__ __half g_wvh [256 * 256];                 // Wv fp16
__device__ float  g_wu256[256];
__device__ float  g_wv256[256];
__device__ float  g_c0_arr[1];
__device__ float  g_u[BATCH * NQ];
__device__ float  g_v[BATCH * NK];

__device__ __forceinline__ void mma_f16(float c[4], const uint32_t a[4], const uint32_t b[2]) {
    asm("mma.sync.aligned.m16n8k16.row.col.f32.f16.f16.f32 "
        "{%0,%1,%2,%3}, {%4,%5,%6,%7}, {%8,%9}, {%0,%1,%2,%3};"
        : "+f"(c[0]), "+f"(c[1]), "+f"(c[2]), "+f"(c[3])
        : "r"(a[0]), "r"(a[1]), "r"(a[2]), "r"(a[3]), "r"(b[0]), "r"(b[1]));
}

__device__ __forceinline__ void ldsm_x4(uint32_t r[4], uint32_t addr) {
    asm volatile("ldmatrix.sync.aligned.m8n8.x4.shared.b16 {%0,%1,%2,%3}, [%4];"
                 : "=r"(r[0]), "=r"(r[1]), "=r"(r[2]), "=r"(r[3]) : "r"(addr));
}

__device__ __forceinline__ void cp_async16(const void* smem, const void* gmem) {
    uint32_t s = (uint32_t)__cvta_generic_to_shared(smem);
    asm volatile("cp.async.cg.shared.global [%0], [%1], 16;" :: "r"(s), "l"(gmem) : "memory");
}
__device__ __forceinline__ void cp_commit() { asm volatile("cp.async.commit_group;" ::: "memory"); }
template<int N> __device__ __forceinline__ void cp_wait() {
    asm volatile("cp.async.wait_group %0;" :: "n"(N) : "memory");
}
__device__ __forceinline__ void stcs_u2(void* p, uint2 v) {
    asm volatile("st.global.cs.v2.u32 [%0], {%1, %2};" :: "l"(p), "r"(v.x), "r"(v.y) : "memory");
}
__device__ __forceinline__ void stcs_f4(void* p, float4 v) {
    asm volatile("st.global.cs.v4.f32 [%0], {%1, %2, %3, %4};"
                 :: "l"(p), "f"(v.x), "f"(v.y), "f"(v.z), "f"(v.w) : "memory");
}

// ---------------- prep kernel: G^T (fp16), wu, wv, c0, Wv fp16 ----------------
__global__ void __launch_bounds__(256) prep_kernel(const float* __restrict__ Wq,
                                                   const float* __restrict__ Wk,
                                                   const float* __restrict__ bq,
                                                   const float* __restrict__ bk,
                                                   const float* __restrict__ Wv) {
    const int bx = blockIdx.x, tid = threadIdx.x;
    if (bx < 256) {
        int e = bx;
        float acc = 0.f;
        for (int d = 0; d < 256; d++)
            acc += Wk[d * 256 + e] * Wq[d * 256 + tid];
        g_Gt[e * 256 + tid] = __float2half_rn(acc * 0.0625f);
    } else if (bx == 256) {
        float acc = 0.f;
        for (int d = 0; d < 256; d++) acc += Wq[d * 256 + tid] * bk[d];
        g_wu256[tid] = acc * 0.0625f;
    } else if (bx == 257) {
        float acc = 0.f;
        for (int d = 0; d < 256; d++) acc += Wk[d * 256 + tid] * bq[d];
        g_wv256[tid] = acc * 0.0625f;
    } else if (bx == 258) {
        __shared__ float red[256];
        red[tid] = bq[tid] * bk[tid];
        __syncthreads();
        for (int s = 128; s; s >>= 1) { if (tid < s) red[tid] += red[tid + s]; __syncthreads(); }
        if (tid == 0) g_c0_arr[0] = red[0] * 0.0625f;
    } else {
        int base = (bx - 259) * 4096 + tid;     // 16 blocks x 4096 = 65536
#pragma unroll
        for (int i = 0; i < 16; i++)
            g_wvh[base + i * 256] = __float2half_rn(Wv[base + i * 256]);
    }
}

// ---------------- aux kernel: fp16 conversions + u/v dots ----------------
// z=0: key rows (B*NK): -> g_k fp16, v[row] = Xk.wv
// z=1: query rows (B*NQ): -> g_xq fp16, u[row] = Xq.wu
// z=2: value rows (B*NK): -> g_xv fp16
__global__ void __launch_bounds__(256) aux_kernel(const float* __restrict__ key,
                                                  const float* __restrict__ query,
                                                  const float* __restrict__ value) {
    const int z = blockIdx.z;
    const long long row = (long long)blockIdx.x * 8 + (threadIdx.x >> 5);
    const int lane = threadIdx.x & 31;
    const long long nrows = (z == 1) ? (long long)BATCH * NQ : (long long)BATCH * NK;
    if (row >= nrows) return;
    const float* X = (z == 0) ? key : (z == 1) ? query : value;
    const float* xr = X + row * 256;
    float4 a  = __ldcs(reinterpret_cast<const float4*>(&xr[lane * 4]));
    float4 b2 = __ldcs(reinterpret_cast<const float4*>(&xr[128 + lane * 4]));

    __half* dst = (z == 0) ? g_k : (z == 1) ? g_xq : g_xv;
    __half2 h0 = __halves2half2(__float2half_rn(a.x),  __float2half_rn(a.y));
    __half2 h1 = __halves2half2(__float2half_rn(a.z),  __float2half_rn(a.w));
    __half2 h2 = __halves2half2(__float2half_rn(b2.x), __float2half_rn(b2.y));
    __half2 h3 = __halves2half2(__float2half_rn(b2.z), __float2half_rn(b2.w));
    uint2 p0, p1;
    p0.x = *reinterpret_cast<uint32_t*>(&h0);
    p0.y = *reinterpret_cast<uint32_t*>(&h1);
    p1.x = *reinterpret_cast<uint32_t*>(&h2);
    p1.y = *reinterpret_cast<uint32_t*>(&h3);
    *reinterpret_cast<uint2*>(&dst[row * 256 + lane * 4])       = p0;
    *reinterpret_cast<uint2*>(&dst[row * 256 + 128 + lane * 4]) = p1;

    if (z < 2) {
        const float* wvec = (z == 0) ? g_wv256 : g_wu256;
        float4 wa = *reinterpret_cast<const float4*>(&wvec[lane * 4]);
        float4 wb = *reinterpret_cast<const float4*>(&wvec[128 + lane * 4]);
        float dot = a.x * wa.x + a.y * wa.y + a.z * wa.z + a.w * wa.w
                  + b2.x * wb.x + b2.y * wb.y + b2.z * wb.z + b2.w * wb.w;
#pragma unroll
        for (int o = 16; o; o >>= 1) dot += __shfl_xor_sync(0xffffffffu, dot, o);
        if (lane == 0) ((z == 0) ? g_v : g_u)[row] = dot;
    }
}

// ======================= fp16 GEMM path =======================

__device__ __forceinline__ void load_tile_h(const __half* a, long long lda,
                                            const __half* b, long long ldb,
                                            __half* sA, __half* sB) {
#pragma unroll
    for (int r = 0; r < 128; r += 32) {
        cp_async16(sA + r * LDSH, a + (long long)r * lda);
        cp_async16(sB + r * LDSH, b + (long long)r * ldb);
    }
    cp_commit();
}

// Warp tile 32x64, ldmatrix fragment loads, A-tile 128 rows.
__device__ __forceinline__ void mma_stage_h(const __half* cA, const __half* cB,
                                            int wm, int wn, int lane,
                                            float (&acc)[2][8][4]) {
    const int lrow16 = lane & 15;
    const int lkoff  = (lane >> 4) << 3;
    uint32_t aAddr = (uint32_t)__cvta_generic_to_shared(
        cA + (wm * 32 + lrow16) * LDSH + lkoff);
    uint32_t bAddr = (uint32_t)__cvta_generic_to_shared(
        cB + (wn * 64 + lrow16) * LDSH + lkoff);
#pragma unroll
    for (int kk = 0; kk < BKH; kk += 16) {
        uint32_t a0[4], a1[4];
        ldsm_x4(a0, aAddr + kk * 2);
        ldsm_x4(a1, aAddr + 16 * LDSH * 2 + kk * 2);
#pragma unroll
        for (int ni2 = 0; ni2 < 4; ni2++) {
            uint32_t bb[4];
            ldsm_x4(bb, bAddr + ni2 * 16 * LDSH * 2 + kk * 2);
            uint32_t be[2] = { bb[0], bb[2] };
            uint32_t bo[2] = { bb[1], bb[3] };
            mma_f16(acc[0][ni2 * 2],     a0, be);
            mma_f16(acc[1][ni2 * 2],     a1, be);
            mma_f16(acc[0][ni2 * 2 + 1], a0, bo);
            mma_f16(acc[1][ni2 * 2 + 1], a1, bo);
        }
    }
}

// Shared fp16 K=256 mainloop (proj and logits)
__device__ __forceinline__ void gemm_loop_h256(const __half* __restrict__ A, long long lda,
                                               const __half* __restrict__ B, long long ldb,
                                               int m0, int n0,
                                               float (&acc)[2][8][4], __half* smemh,
                                               int wm, int wn, int lane,
                                               int lrow, int lcol) {
    const __half* Ag = A + (long long)(m0 + lrow) * lda + lcol;
    const __half* Bg = B + (long long)(n0 + lrow) * ldb + lcol;
    __half* sA0 = smemh + lrow * LDSH + lcol;
    __half* sB0 = smemh + TILE_H + lrow * LDSH + lcol;

    const int kt = DMODEL / BKH;   // 4
    load_tile_h(Ag, lda, Bg, ldb, sA0, sB0);
    for (int it = 0; it < kt; ++it) {
        int nxt = (it + 1) & 1;
        if (it + 1 < kt) {
            load_tile_h(Ag + (it + 1) * BKH, lda, Bg + (it + 1) * BKH, ldb,
                        sA0 + nxt * BUFSTR_H, sB0 + nxt * BUFSTR_H);
            cp_wait<1>();
        } else {
            cp_wait<0>();
        }
        __syncthreads();
        mma_stage_h(smemh + (it & 1) * BUFSTR_H,
                    smemh + (it & 1) * BUFSTR_H + TILE_H,
                    wm, wn, lane, acc);
        __syncthreads();
    }
}

// ---------------- proj kernel (fp16) ----------------
// z = 0: t = Xq @ Gt -> g_q fp16 (grid.x < 256)
// z = 1: v = Xv @ Wv + bv -> g_vT fp16 (transposed)
__global__ void __launch_bounds__(256) proj_kernel(const float* __restrict__ bv) {
    extern __shared__ __half smemh[];
    const int z = blockIdx.z;
    if (z == 0 && blockIdx.x >= BATCH * NQ / BM) return;

    const __half* A = z ? g_xv : g_xq;
    const __half* B = z ? g_wvh : g_Gt;

    const int tid = threadIdx.x, warp = tid >> 5, lane = tid & 31;
    const int wm = warp >> 1, wn = warp & 1, g = lane >> 2, tg = lane & 3;
    const int lrow = tid >> 3;
    const int lcol = (tid & 7) << 3;

    float acc[2][8][4] = {};
    const int m0 = blockIdx.x * BM, n0 = blockIdx.y * BN;
    gemm_loop_h256(A, DMODEL, B, DMODEL, m0, n0, acc, smemh, wm, wn, lane, lrow, lcol);

#pragma unroll
    for (int mi = 0; mi < 2; mi++) {
#pragma unroll
        for (int half = 0; half < 2; half++) {
            int r = m0 + wm * 32 + mi * 16 + g + half * 8;
#pragma unroll
            for (int ni = 0; ni < 8; ni++) {
                int c = n0 + wn * 64 + ni * 8 + tg * 2;
                if (z == 0) {
                    __half h0 = __float2half_rn(acc[mi][ni][half * 2 + 0]);
                    __half h1 = __float2half_rn(acc[mi][ni][half * 2 + 1]);
                    *reinterpret_cast<__half2*>(&g_q[(long long)r * DMODEL + c]) =
                        __halves2half2(h0, h1);
                } else {
                    float v0 = acc[mi][ni][half * 2 + 0] + bv[c];
                    float v1 = acc[mi][ni][half * 2 + 1] + bv[c + 1];
                    long long bidx = r >> 11;               // NK = 2048
                    long long tk = r & (NK - 1);
                    g_vT[(bidx * DMODEL + c) * NK + tk]     = __float2half_rn(v0);
                    g_vT[(bidx * DMODEL + c + 1) * NK + tk] = __float2half_rn(v1);
                }
            }
        }
    }
}

// ---------------- Logits kernel (fp16, + u/v/c bilinear terms) ----------------
__global__ void __launch_bounds__(256) logits_kernel(const float* __restrict__ bias,
                                                     const int* __restrict__ qmask,
                                                     const int* __restrict__ kmask) {
    extern __shared__ __half smemh[];
    const int b = blockIdx.z;
    const int m0 = blockIdx.x * BM, n0 = blockIdx.y * BN;

    const int tid  = threadIdx.x;
    const int warp = tid >> 5, lane = tid & 31;
    const int wm = warp >> 1, wn = warp & 1;
    const int g  = lane >> 2, tg = lane & 3;
    const int lrow = tid >> 3;
    const int lcol = (tid & 7) << 3;

    float acc[2][8][4] = {};
    gemm_loop_h256(g_q + (long long)b * NQ * DMODEL, DMODEL,
                   g_k + (long long)b * NK * DMODEL, DMODEL,
                   m0, n0, acc, smemh, wm, wn, lane, lrow, lcol);

    // scatter raw (already /16-scaled) logit mains to fp32 smem tile
    float* st = reinterpret_cast<float*>(smemh);
#pragma unroll
    for (int mi = 0; mi < 2; mi++) {
#pragma unroll
        for (int half = 0; half < 2; half++) {
            int rl = wm * 32 + mi * 16 + half * 8 + g;
#pragma unroll
            for (int ni = 0; ni < 8; ni++) {
                int c = wn * 64 + ni * 8 + tg * 2;
                st[rl * LDS2 + c]     = acc[mi][ni][half * 2 + 0];
                st[rl * LDS2 + c + 1] = acc[mi][ni][half * 2 + 1];
            }
        }
    }
    __syncthreads();

    const int4 km4 = *reinterpret_cast<const int4*>(&kmask[b * NK + n0 + lane * 4]);
    const int* qm = qmask + b * NQ;
    const float* bb = bias + ((long long)b * NQ + m0) * NK + n0;
    __half* eb = g_e + ((long long)b * NQ + m0) * NK + n0;
    const float c0 = g_c0_arr[0];
    const float4 v4 = *reinterpret_cast<const float4*>(&g_v[b * NK + n0 + lane * 4]);
    const float* up = g_u + (long long)b * NQ + m0;

    // Software-pipelined row loop: bias for row rr+1 issued before row rr's exp chain.
    float4 bv_next = __ldcs(reinterpret_cast<const float4*>(
        &bb[(long long)(warp * 16) * NK + lane * 4]));
#pragma unroll 4
    for (int rr = 0; rr < 16; rr++) {
        int rl = warp * 16 + rr;
        float4 bv = bv_next;
        if (rr + 1 < 16)
            bv_next = __ldcs(reinterpret_cast<const float4*>(
                &bb[(long long)(rl + 1) * NK + lane * 4]));
        int qv = qm[m0 + rl];
        float uv = up[rl] + c0;
        float4 l4 = *reinterpret_cast<const float4*>(&st[rl * LDS2 + lane * 4]);
        float e0, e1, e2, e3;
        if (qv) {
            e0 = km4.x ? fminf(__expf(l4.x + bv.x + v4.x + uv), 60000.f) : 0.f;
            e1 = km4.y ? fminf(__expf(l4.y + bv.y + v4.y + uv), 60000.f) : 0.f;
            e2 = km4.z ? fminf(__expf(l4.z + bv.z + v4.z + uv), 60000.f) : 0.f;
            e3 = km4.w ? fminf(__expf(l4.w + bv.w + v4.w + uv), 60000.f) : 0.f;
        } else {
            e0 = e1 = e2 = e3 = 1.f;   // fully-masked row -> uniform softmax
        }
        __half2 h01 = __halves2half2(__float2half_rn(e0), __float2half_rn(e1));
        __half2 h23 = __halves2half2(__float2half_rn(e2), __float2half_rn(e3));
        uint2 packed;
        packed.x = *reinterpret_cast<uint32_t*>(&h01);
        packed.y = *reinterpret_cast<uint32_t*>(&h23);
        stcs_u2(&eb[(long long)rl * NK + lane * 4], packed);
        float vsum = __half2float(__low2half(h01)) + __half2float(__high2half(h01))
                   + __half2float(__low2half(h23)) + __half2float(__high2half(h23));
#pragma unroll
        for (int off = 16; off; off >>= 1)
            vsum += __shfl_xor_sync(0xffffffffu, vsum, off);
        if (lane == 0)
            g_psum[((b * 16 + blockIdx.y) << 10) + m0 + rl] = vsum;
    }
}

// ---------------- Output GEMM (fp16, BM=64, combine fused) ----------------
__global__ void __launch_bounds__(256) out_kernel(float* __restrict__ wout,
                                                  float* __restrict__ out) {
    extern __shared__ __half smemh[];
    float* sI = reinterpret_cast<float*>(smemh + 2 * BUFSTR_O);   // [64]

    const int b = blockIdx.z;
    const int m0 = blockIdx.x * 64, n0 = blockIdx.y * BN;
    const int tid = threadIdx.x;
    const int warp = tid >> 5, lane = tid & 31;
    const int wm = warp >> 2, wn = warp & 3;

    if (tid < 64) {
        float S = 0.f;
#pragma unroll
        for (int nt = 0; nt < 16; nt++)
            S += g_psum[((b * 16 + nt) << 10) + m0 + tid];
        sI[tid] = 1.0f / S;
    }

    const __half* A = g_e + (long long)b * NQ * NK;
    const __half* B = g_vT + (long long)b * DMODEL * NK;
    float* wb = wout + (long long)b * NQ * NK;
    const bool first_half = (n0 == 0);

    const int lrow = tid >> 3;
    const int lcol = (tid & 7) << 3;
    const __half* Ag = A + (long long)(m0 + lrow) * NK + lcol;
    const __half* Bg = B + (long long)(n0 + lrow) * NK + lcol;
    __half* sA0 = smemh + lrow * LDSH + lcol;
    __half* sB0 = smemh + TILE_A64 + lrow * LDSH + lcol;

    float acc[2][4][4] = {};
    const int kt = NK / BKH;   // 32

#define LOAD_TILE_O(koff, stg)                                                     \
    do {                                                                           \
        const __half* _a = Ag + (koff);                                            \
        const __half* _b = Bg + (koff);                                            \
        __half* _sa = sA0 + (stg) * BUFSTR_O;                                      \
        __half* _sb = sB0 + (stg) * BUFSTR_O;                                      \
        cp_async16(_sa, _a);                                                       \
        cp_async16(_sa + 32 * LDSH, _a + 32ll * NK);                               \
        cp_async16(_sb, _b);                                                       \
        cp_async16(_sb + 32 * LDSH, _b + 32ll * NK);                               \
        cp_async16(_sb + 64 * LDSH, _b + 64ll * NK);                               \
        cp_async16(_sb + 96 * LDSH, _b + 96ll * NK);                               \
        cp_commit();                                                               \
    } while (0)

    LOAD_TILE_O(0, 0);

    const int wrow = tid >> 2, wseg = tid & 3;

    for (int it = 0; it < kt; ++it) {
        int nxt = (it + 1) & 1;
        if (it + 1 < kt) {
            LOAD_TILE_O((it + 1) * BKH, nxt);
            cp_wait<1>();
        } else {
            cp_wait<0>();
        }
        __syncthreads();

        __half* bufA = smemh + (it & 1) * BUFSTR_O;
        __half* bufB = bufA + TILE_A64;

        if ((it < kt / 2) == first_half) {
            const int k0 = it * BKH;
            float rI = sI[wrow];
            float* wr = wb + (long long)(m0 + wrow) * NK + k0 + wseg * 16;
            const __half* src = bufA + wrow * LDSH + wseg * 16;
#pragma unroll
            for (int j = 0; j < 2; j++) {
                uint4 raw = *reinterpret_cast<const uint4*>(src + j * 8);
                __half2 p0 = *reinterpret_cast<__half2*>(&raw.x);
                __half2 p1 = *reinterpret_cast<__half2*>(&raw.y);
                __half2 p2 = *reinterpret_cast<__half2*>(&raw.z);
                __half2 p3 = *reinterpret_cast<__half2*>(&raw.w);
                float4 o0, o1;
                o0.x = __half2float(__low2half(p0)) * rI;
                o0.y = __half2float(__high2half(p0)) * rI;
                o0.z = __half2float(__low2half(p1)) * rI;
                o0.w = __half2float(__high2half(p1)) * rI;
                o1.x = __half2float(__low2half(p2)) * rI;
                o1.y = __half2float(__high2half(p2)) * rI;
                o1.z = __half2float(__low2half(p3)) * rI;
                o1.w = __half2float(__high2half(p3)) * rI;
                stcs_f4(wr + j * 8,     o0);
                stcs_f4(wr + j * 8 + 4, o1);
            }
        }

        {
            const int lrow16 = lane & 15;
            const int lkoff  = (lane >> 4) << 3;
            uint32_t aAddr = (uint32_t)__cvta_generic_to_shared(
                bufA + (wm * 32 + lrow16) * LDSH + lkoff);
            uint32_t bAddr = (uint32_t)__cvta_generic_to_shared(
                bufB + (wn * 32 + lrow16) * LDSH + lkoff);
#pragma unroll
            for (int kk = 0; kk < BKH; kk += 16) {
                uint32_t a0[4], a1[4];
                ldsm_x4(a0, aAddr + kk * 2);
                ldsm_x4(a1, aAddr + 16 * LDSH * 2 + kk * 2);
#pragma unroll
                for (int ni2 = 0; ni2 < 2; ni2++) {
                    uint32_t bbf[4];
                    ldsm_x4(bbf, bAddr + ni2 * 16 * LDSH * 2 + kk * 2);
                    uint32_t be[2] = { bbf[0], bbf[2] };
                    uint32_t bo[2] = { bbf[1], bbf[3] };
                    mma_f16(acc[0][ni2 * 2],     a0, be);
                    mma_f16(acc[1][ni2 * 2],     a1, be);
                    mma_f16(acc[0][ni2 * 2 + 1], a0, bo);
                    mma_f16(acc[1][ni2 * 2 + 1], a1, bo);
                }
            }
        }
        __syncthreads();
    }

    float* ob = out + (long long)b * NQ * DMODEL;
    const int g = lane >> 2, tg = lane & 3;
#pragma unroll
    for (int mi = 0; mi < 2; mi++) {
#pragma unroll
        for (int half = 0; half < 2; half++) {
            int rl = wm * 32 + mi * 16 + g + half * 8;
            int r = m0 + rl;
            float rI = sI[rl];
#pragma unroll
            for (int ni = 0; ni < 4; ni++) {
#pragma unroll
                for (int cj = 0; cj < 2; cj++) {
                    int c = n0 + wn * 32 + ni * 8 + tg * 2 + cj;
                    ob[(long long)r * DMODEL + c] = acc[mi][ni][half * 2 + cj] * rI;
                }
            }
        }
    }
}

extern "C" void kernel_launch(void* const* d_in, const int* in_sizes, int n_in,
                              void* d_out, int out_size) {
    (void)in_sizes; (void)n_in; (void)out_size;
    const float* query = (const float*)d_in[0];
    const float* key   = (const float*)d_in[1];
    const float* value = (const float*)d_in[2];
    const int*   qmask = (const int*)d_in[3];
    const int*   kmask = (const int*)d_in[4];
    const float* bias  = (const float*)d_in[5];
    const float* Wq = (const float*)d_in[6];
    const float* bq = (const float*)d_in[7];
    const float* Wk = (const float*)d_in[8];
    const float* bk = (const float*)d_in[9];
    const float* Wv = (const float*)d_in[10];
    const float* bv = (const float*)d_in[11];

    float* out = (float*)d_out;                                   // (B, NQ, D)
    float* w   = out + (size_t)BATCH * NQ * DMODEL;               // (B, NQ, NK)

    cudaFuncSetAttribute((const void*)proj_kernel,   cudaFuncAttributeMaxDynamicSharedMemorySize, SMEM_H);
    cudaFuncSetAttribute((const void*)logits_kernel, cudaFuncAttributeMaxDynamicSharedMemorySize, SMEM_H);
    cudaFuncSetAttribute((const void*)out_kernel,    cudaFuncAttributeMaxDynamicSharedMemorySize, SMEM_O);

    // G^T (fp16), wu, wv, c0, Wv fp16
    prep_kernel<<<275, 256>>>(Wq, Wk, bq, bk, Wv);

    // fp16 conversions + u/v dots
    aux_kernel<<<dim3(BATCH * NK / 8, 1, 3), 256>>>(key, query, value);

    // t = Xq @ Gt (z=0, x<256); v-proj (z=1) — both fp16
    proj_kernel<<<dim3(BATCH * NK / BM, DMODEL / BN, 2), 256, SMEM_H>>>(bv);

    // e = exp(t.Xk + u + v + c + bias) fp16 + per-tile row sums
    logits_kernel<<<dim3(NQ / BM, NK / BN, BATCH), 256, SMEM_H>>>(bias, qmask, kmask);

    // out = invS * (e @ v); combine fused; streams w = e * invS
    out_kernel<<<dim3(NQ / 64, DMODEL / BN, BATCH), 256, SMEM_O>>>(w, out);
}